// round 17
// baseline (speedup 1.0000x reference)
#include <cuda_runtime.h>
#include <cuda_bf16.h>
#include <cstdint>

#define NROWS 32768
#define KDIM  512
#define NQKV  1536
#define NINST 8192

// ---------------- device scratch (referenced ONLY in device code) ----------
__device__ __align__(16) float          g_qkv[(size_t)NROWS * NQKV];
__device__ __align__(16) unsigned short g_xnhi[(size_t)NROWS * KDIM];
__device__ __align__(16) unsigned short g_xnlo[(size_t)NROWS * KDIM];
__device__ __align__(16) unsigned short g_vhhi[(size_t)NROWS * KDIM];
__device__ __align__(16) unsigned short g_vhlo[(size_t)NROWS * KDIM];
__device__ __align__(16) unsigned short g_wqhi[(size_t)NQKV * KDIM];   // W_qkv^T [N][K]
__device__ __align__(16) unsigned short g_wqlo[(size_t)NQKV * KDIM];
__device__ __align__(16) unsigned short g_wohi[(size_t)KDIM * KDIM];   // W_out^T [N][K]
__device__ __align__(16) unsigned short g_wolo[(size_t)KDIM * KDIM];

__device__ __forceinline__ void bfsplit(float v, unsigned short& hi, unsigned short& lo) {
    __nv_bfloat16 h = __float2bfloat16(v);
    float r = v - __bfloat162float(h);
    __nv_bfloat16 l = __float2bfloat16(r);
    hi = __bfloat16_as_ushort(h);
    lo = __bfloat16_as_ushort(l);
}

__device__ __forceinline__ uint32_t smem_u32(const void* p) {
    uint32_t a;
    asm("{ .reg .u64 t; cvta.to.shared.u64 t, %1; cvt.u32.u64 %0, t; }" : "=r"(a) : "l"(p));
    return a;
}
__device__ __forceinline__ void cp16(uint32_t saddr, const void* g) {
    asm volatile("cp.async.cg.shared.global [%0], [%1], 16;" :: "r"(saddr), "l"(g));
}
__device__ __forceinline__ void ldsm_x4(uint32_t* r, uint32_t addr) {
    asm volatile("ldmatrix.sync.aligned.m8n8.x4.shared.b16 {%0,%1,%2,%3}, [%4];"
                 : "=r"(r[0]), "=r"(r[1]), "=r"(r[2]), "=r"(r[3]) : "r"(addr));
}
__device__ __forceinline__ void mma16816(float* c, const uint32_t* a, uint32_t b0, uint32_t b1) {
    asm volatile("mma.sync.aligned.m16n8k16.row.col.f32.bf16.bf16.f32 "
                 "{%0,%1,%2,%3}, {%4,%5,%6,%7}, {%8,%9}, {%0,%1,%2,%3};"
                 : "+f"(c[0]), "+f"(c[1]), "+f"(c[2]), "+f"(c[3])
                 : "r"(a[0]), "r"(a[1]), "r"(a[2]), "r"(a[3]), "r"(b0), "r"(b1));
}

// ---------------------------------------------------------------------------
// Prep kernel: LN (blocks 0..4095) + W_qkv split (4096..4863) + W_out split
// (4864..5119).
// ---------------------------------------------------------------------------
__global__ __launch_bounds__(256) void prep_kernel(const float* __restrict__ x,
                                                   const float* __restrict__ gamma,
                                                   const float* __restrict__ beta,
                                                   const float* __restrict__ Wq,
                                                   const float* __restrict__ Wo)
{
    __shared__ float t[32][33];
    const int nb = blockIdx.x;

    if (nb < 4096) {
        int row  = (nb * 256 + threadIdx.x) >> 5;
        int lane = threadIdx.x & 31;

        const float4* xr = (const float4*)(x + (size_t)row * KDIM);
        float4 v[4];
        float s = 0.f, ss = 0.f;
#pragma unroll
        for (int i = 0; i < 4; i++) {
            v[i] = xr[lane + i * 32];
            s  += v[i].x + v[i].y + v[i].z + v[i].w;
            ss += v[i].x * v[i].x + v[i].y * v[i].y + v[i].z * v[i].z + v[i].w * v[i].w;
        }
#pragma unroll
        for (int o = 16; o; o >>= 1) {
            s  += __shfl_xor_sync(0xffffffffu, s, o);
            ss += __shfl_xor_sync(0xffffffffu, ss, o);
        }
        float mean = s * (1.0f / KDIM);
        float inv  = rsqrtf(ss * (1.0f / KDIM) - mean * mean + 1e-5f);

        const float4* g4 = (const float4*)gamma;
        const float4* b4 = (const float4*)beta;
#pragma unroll
        for (int i = 0; i < 4; i++) {
            int idx = lane + i * 32;
            float4 g = g4[idx], b = b4[idx], r;
            r.x = (v[i].x - mean) * inv * g.x + b.x;
            r.y = (v[i].y - mean) * inv * g.y + b.y;
            r.z = (v[i].z - mean) * inv * g.z + b.z;
            r.w = (v[i].w - mean) * inv * g.w + b.w;
            __align__(8) unsigned short h4[4], l4[4];
            bfsplit(r.x, h4[0], l4[0]); bfsplit(r.y, h4[1], l4[1]);
            bfsplit(r.z, h4[2], l4[2]); bfsplit(r.w, h4[3], l4[3]);
            size_t e = (size_t)row * KDIM + idx * 4;
            *(uint2*)(g_xnhi + e) = *(uint2*)h4;
            *(uint2*)(g_xnlo + e) = *(uint2*)l4;
        }
    } else {
        const bool isq = nb < 4864;
        const int tix  = isq ? (nb - 4096) : (nb - 4864);
        const int NBX  = isq ? 48 : 16;
        const int bx = tix % NBX, by = tix / NBX;
        const float* W = isq ? Wq : Wo;
        unsigned short* Thi = isq ? g_wqhi : g_wohi;
        unsigned short* Tlo = isq ? g_wqlo : g_wolo;
        const int N = isq ? NQKV : KDIM;

        int xo = bx * 32, yo = by * 32;
        int tx = threadIdx.x & 31, ty = threadIdx.x >> 5;
#pragma unroll
        for (int j = 0; j < 4; j++)
            t[ty + 8 * j][tx] = W[(size_t)(yo + ty + 8 * j) * N + xo + tx];
        __syncthreads();
#pragma unroll
        for (int j = 0; j < 4; j++) {
            float v = t[tx][ty + 8 * j];
            int n = xo + ty + 8 * j, k = yo + tx;
            unsigned short hi, lo;
            bfsplit(v, hi, lo);
            Thi[(size_t)n * KDIM + k] = hi;
            Tlo[(size_t)n * KDIM + k] = lo;
        }
    }
}

// ---------------------------------------------------------------------------
// RAW mma.sync bf16 split GEMM, 3-STAGE cp.async ring.
// R16 analysis: `wait_group 0` waited for the tile issued IN THE SAME
// iteration (copy had only half an iteration to land) -> exposed global
// latency every iter, tensor capped at 58.5%. Now each tile is issued two
// iterations ahead: wait_group 1 at iter kt waits for tile kt (issued kt-2).
// One __syncthreads per iter; the sync precedes ISSUE so stage (kt+2)%3
// (last read at kt-1) is provably free. Block 128x64, BK=32, 8 warps (4x2),
// warp tile 32x32, smem 3x30KB=90KB -> still 2 CTAs/SM. Stride 40 bf16
// (conflict-free LDSM). !ISQKV adds bias in the register epilogue.
// ---------------------------------------------------------------------------
template<bool ISQKV>
__global__ __launch_bounds__(256, 2) void mma_gemm_kernel(const float* __restrict__ bias,
                                                          float* __restrict__ Cout)
{
    extern __shared__ __align__(16) __nv_bfloat16 sdyn[];
    // stage base (elements) = stg*15360:
    //   Ahi +0 (128x40), Alo +5120, Bhi +10240 (64x40), Blo +12800

    const int N = ISQKV ? NQKV : KDIM;
    const unsigned short* pA[2] = { ISQKV ? g_xnhi : g_vhhi, ISQKV ? g_xnlo : g_vhlo };
    const unsigned short* pB[2] = { ISQKV ? g_wqhi : g_wohi, ISQKV ? g_wqlo : g_wolo };
    float* C = ISQKV ? g_qkv : Cout;

    const int tid = threadIdx.x, wid = tid >> 5, lane = tid & 31;
    const int wm = wid >> 1;            // 0..3 -> m offset 32*wm
    const int wn = wid & 1;             // 0..1 -> n offset 32*wn
    const int m0 = blockIdx.y * 128, n0 = blockIdx.x * 64;
    const uint32_t sb = smem_u32(sdyn);

    const int a_eoff = (wm * 32 + (lane & 15)) * 40 + ((lane >> 4) << 3);
    const int b_eoff = (wn * 32 + ((lane >> 4) << 3) + (lane & 7)) * 40 + (((lane >> 3) & 1) << 3);

    const uint32_t aAddr0 = sb + 2u * (0     + a_eoff);
    const uint32_t aAddr1 = sb + 2u * (5120  + a_eoff);
    const uint32_t bAddr0 = sb + 2u * (10240 + b_eoff);
    const uint32_t bAddr1 = sb + 2u * (12800 + b_eoff);

    float acc[2][4][4];
#pragma unroll
    for (int i = 0; i < 2; i++)
#pragma unroll
        for (int j = 0; j < 4; j++)
#pragma unroll
            for (int q = 0; q < 4; q++) acc[i][j][q] = 0.f;

#define ISSUE_TILE(KT, STG) do { \
    const int _k0 = (KT) * 32; \
    const uint32_t _sbase = sb + (uint32_t)((STG) * 15360 * 2); \
    _Pragma("unroll") \
    for (int t = 0; t < 6; t++) { \
        int cid = tid + t * 256; \
        if (cid < 1024) { \
            int s = cid >> 9, r = (cid >> 2) & 127, kc = cid & 3; \
            cp16(_sbase + (uint32_t)((s * 5120 + r * 40 + kc * 8) * 2), \
                 pA[s] + (size_t)(m0 + r) * KDIM + _k0 + kc * 8); \
        } else { \
            int c = cid - 1024; \
            int s = c >> 8, r = (c >> 2) & 63, kc = c & 3; \
            cp16(_sbase + (uint32_t)((10240 + s * 2560 + r * 40 + kc * 8) * 2), \
                 pB[s] + (size_t)(n0 + r) * KDIM + _k0 + kc * 8); \
        } \
    } \
    asm volatile("cp.async.commit_group;"); \
} while (0)

    uint32_t fa0[2][2][4], fb0[2][2][4];
    uint32_t fa1[2][2][4], fb1[2][2][4];

#define LOADF(FA, FB, STG, KS) do { \
    const uint32_t _o = 2u * ((uint32_t)(STG) * 15360 + (KS) * 16); \
    _Pragma("unroll") \
    for (int mt = 0; mt < 2; mt++) { \
        ldsm_x4(FA[0][mt], aAddr0 + _o + 2u * (mt * 640)); \
        ldsm_x4(FA[1][mt], aAddr1 + _o + 2u * (mt * 640)); \
    } \
    _Pragma("unroll") \
    for (int hf = 0; hf < 2; hf++) { \
        ldsm_x4(FB[0][hf], bAddr0 + _o + 2u * (hf * 640)); \
        ldsm_x4(FB[1][hf], bAddr1 + _o + 2u * (hf * 640)); \
    } \
} while (0)

#define DOMMA(FA, FB) do { \
    _Pragma("unroll") \
    for (int mt = 0; mt < 2; mt++) \
        _Pragma("unroll") \
        for (int j = 0; j < 4; j++) { \
            const int hf = j >> 1, sub = j & 1; \
            float* cc = acc[mt][j]; \
            mma16816(cc, FA[0][mt], FB[0][hf][sub * 2], FB[0][hf][sub * 2 + 1]); \
            mma16816(cc, FA[0][mt], FB[1][hf][sub * 2], FB[1][hf][sub * 2 + 1]); \
            mma16816(cc, FA[1][mt], FB[0][hf][sub * 2], FB[0][hf][sub * 2 + 1]); \
        } \
} while (0)

    ISSUE_TILE(0, 0);
    ISSUE_TILE(1, 1);

    int stg = 0;
#pragma unroll 1
    for (int kt = 0; kt < 16; kt++) {
        if (kt < 15) asm volatile("cp.async.wait_group 1;" ::: "memory");
        else         asm volatile("cp.async.wait_group 0;" ::: "memory");
        __syncthreads();                     // tile kt visible; stage (kt+2)%3 free
        if (kt + 2 < 16) {
            int ns = stg + 2; if (ns >= 3) ns -= 3;
            ISSUE_TILE(kt + 2, ns);
        }
        LOADF(fa0, fb0, stg, 0);
        LOADF(fa1, fb1, stg, 1);
        DOMMA(fa0, fb0);
        DOMMA(fa1, fb1);
        stg = (stg == 2) ? 0 : stg + 1;
    }

    // epilogue: c-frag rows lane>>2 (+8), cols (lane&3)*2 within n8 tile j
#pragma unroll
    for (int mt = 0; mt < 2; mt++) {
        const int m = m0 + wm * 32 + mt * 16 + (lane >> 2);
#pragma unroll
        for (int j = 0; j < 4; j++) {
            const int col = n0 + wn * 32 + j * 8 + (lane & 3) * 2;
            float b0 = 0.f, b1 = 0.f;
            if (!ISQKV) { b0 = __ldg(bias + col); b1 = __ldg(bias + col + 1); }
            *(float2*)(C + (size_t)m * N + col)       = make_float2(acc[mt][j][0] + b0, acc[mt][j][1] + b1);
            *(float2*)(C + (size_t)(m + 8) * N + col) = make_float2(acc[mt][j][2] + b0, acc[mt][j][3] + b1);
        }
    }
#undef ISSUE_TILE
#undef LOADF
#undef DOMMA
}

// ---------------------------------------------------------------------------
// Attention: one block per instance (8192). Conflict-free smem layout.
// ---------------------------------------------------------------------------
__global__ __launch_bounds__(256) void attn_kernel()
{
    __shared__ float sQ[32][68];
    __shared__ float sKT[64][36];
    __shared__ float sV[32][68];
    __shared__ float S[32 * 33];

    const int inst = blockIdx.x;
    const int d2 = inst & 15;
    const int c2 = (inst >> 4) & 15;
    const int h  = (inst >> 8) & 7;
    const int b  = inst >> 11;
    const int c  = 2 * h + (c2 >> 3);
    const int d  = 2 * (c2 & 7) + (d2 >> 3);
    const int wb = 4 * (d2 & 7);
    const size_t rowIdx  = (((size_t)(b * 16 + c) * 16 + d) * 32 + wb);
    const size_t srcBase = rowIdx * 1536;
    const size_t dstBase = rowIdx * 512;

    const int tid = threadIdx.x;
    const float4* src4 = (const float4*)(g_qkv + srcBase);

#pragma unroll
    for (int it = 0; it < 6; it++) {
        int p = tid + it * 256;
        float4 v = src4[p];
        int r  = p / 384;
        int f  = p - r * 384;
        int o  = f / 48;
        int t4 = f - o * 48;
        int sec = t4 >> 4;         // 0=Q 1=K 2=V
        int e   = (t4 & 15) * 4;
        int w2  = r * 8 + o;
        if (sec == 0)      *(float4*)&sQ[w2][e] = v;
        else if (sec == 2) *(float4*)&sV[w2][e] = v;
        else {
            sKT[e + 0][w2] = v.x;
            sKT[e + 1][w2] = v.y;
            sKT[e + 2][w2] = v.z;
            sKT[e + 3][w2] = v.w;
        }
    }
    __syncthreads();

    {
        const int i  = tid >> 3;
        const int jg = (tid & 7) * 4;
        const float* qr = sQ[i];
        float s0 = 0.f, s1 = 0.f, s2 = 0.f, s3 = 0.f;
#pragma unroll
        for (int e4 = 0; e4 < 64; e4 += 4) {
            float4 q4 = *(const float4*)(qr + e4);
            float4 ka = *(const float4*)&sKT[e4 + 0][jg];
            float4 kb = *(const float4*)&sKT[e4 + 1][jg];
            float4 kc = *(const float4*)&sKT[e4 + 2][jg];
            float4 kd = *(const float4*)&sKT[e4 + 3][jg];
            s0 = fmaf(q4.x, ka.x, s0); s1 = fmaf(q4.x, ka.y, s1);
            s2 = fmaf(q4.x, ka.z, s2); s3 = fmaf(q4.x, ka.w, s3);
            s0 = fmaf(q4.y, kb.x, s0); s1 = fmaf(q4.y, kb.y, s1);
            s2 = fmaf(q4.y, kb.z, s2); s3 = fmaf(q4.y, kb.w, s3);
            s0 = fmaf(q4.z, kc.x, s0); s1 = fmaf(q4.z, kc.y, s1);
            s2 = fmaf(q4.z, kc.z, s2); s3 = fmaf(q4.z, kc.w, s3);
            s0 = fmaf(q4.w, kd.x, s0); s1 = fmaf(q4.w, kd.y, s1);
            s2 = fmaf(q4.w, kd.z, s2); s3 = fmaf(q4.w, kd.w, s3);
        }
        S[i * 33 + jg + 0] = s0 * 8.0f;
        S[i * 33 + jg + 1] = s1 * 8.0f;
        S[i * 33 + jg + 2] = s2 * 8.0f;
        S[i * 33 + jg + 3] = s3 * 8.0f;
    }
    __syncthreads();

    {
        const int warp = tid >> 5, lane = tid & 31;
#pragma unroll
        for (int r = 0; r < 4; r++) {
            int i = warp * 4 + r;
            float v = S[i * 33 + lane];
            float m = v;
#pragma unroll
            for (int o = 16; o; o >>= 1) m = fmaxf(m, __shfl_xor_sync(0xffffffffu, m, o));
            float p = __expf(v - m);
            float s = p;
#pragma unroll
            for (int o = 16; o; o >>= 1) s += __shfl_xor_sync(0xffffffffu, s, o);
            S[i * 33 + lane] = p * __frcp_rn(s);
        }
    }
    __syncthreads();

    {
        const int i  = tid >> 3;
        const int eg = (tid & 7) * 8;
        float acc[8] = {0.f,0.f,0.f,0.f,0.f,0.f,0.f,0.f};
#pragma unroll
        for (int j = 0; j < 32; j++) {
            float a = S[i * 33 + j];
            float4 v0 = *(const float4*)&sV[j][eg];
            float4 v1 = *(const float4*)&sV[j][eg + 4];
            acc[0] += a*v0.x; acc[1] += a*v0.y; acc[2] += a*v0.z; acc[3] += a*v0.w;
            acc[4] += a*v1.x; acc[5] += a*v1.y; acc[6] += a*v1.z; acc[7] += a*v1.w;
        }
        __align__(16) unsigned short h8[8], l8[8];
#pragma unroll
        for (int q = 0; q < 8; q++) bfsplit(acc[q], h8[q], l8[q]);
        size_t o = dstBase + (size_t)(i >> 3) * 512 + (i & 7) * 64 + eg;
        *(uint4*)(g_vhhi + o) = *(uint4*)h8;
        *(uint4*)(g_vhlo + o) = *(uint4*)l8;
    }
}

// ---------------------------------------------------------------------------
extern "C" void kernel_launch(void* const* d_in, const int* in_sizes, int n_in,
                              void* d_out, int out_size)
{
    if (n_in < 6) return;
    int used[32];
    for (int i = 0; i < 32; i++) used[i] = 0;
    int big[3] = {-1, -1, -1};
    for (int r = 0; r < 3; r++) {
        int best = -1; long long bs = -1;
        for (int i = 0; i < n_in && i < 32; i++) {
            if (used[i]) continue;
            if ((long long)in_sizes[i] > bs) { bs = (long long)in_sizes[i]; best = i; }
        }
        if (best < 0) return;
        big[r] = best; used[best] = 1;
    }
    const float* x     = (const float*)d_in[big[0]];
    const float* W_qkv = (const float*)d_in[big[1]];
    const float* W_out = (const float*)d_in[big[2]];
    const float* vecs[3] = {nullptr, nullptr, nullptr};
    int nv = 0;
    for (int i = 0; i < n_in && i < 32; i++)
        if (!used[i] && nv < 3) vecs[nv++] = (const float*)d_in[i];
    if (nv < 3 || !x || !W_qkv || !W_out) return;

    const float* gamma = vecs[0];
    const float* beta  = vecs[1];
    const float* b_out = vecs[2];
    float* out = (float*)d_out;

    const int GSM = 92160;   // 3 stages x 30720 B
    cudaFuncSetAttribute(mma_gemm_kernel<true>,  cudaFuncAttributeMaxDynamicSharedMemorySize, GSM);
    cudaFuncSetAttribute(mma_gemm_kernel<false>, cudaFuncAttributeMaxDynamicSharedMemorySize, GSM);

    prep_kernel<<<5120, 256>>>(x, gamma, beta, W_qkv, W_out);
    mma_gemm_kernel<true><<<dim3(NQKV / 64, NROWS / 128), 256, GSM>>>(nullptr, nullptr);
    attn_kernel<<<NINST, 256>>>();
    mma_gemm_kernel<false><<<dim3(KDIM / 64, NROWS / 128), 256, GSM>>>(b_out, out);
}